// round 6
// baseline (speedup 1.0000x reference)
#include <cuda_runtime.h>

// SigMMDLoss: B=4096 rows, T=4096, two input tensors (real, gen), scalar f32 out.
//
// Per-row (N = T-1 = 4095 increments dx_k = p[k+1]-p[k]):
//   f1 = sum dx            = p[N] - p[0]                        (telescoped)
//   f3 = dt*sum (k+1)dx    = p[N] - (sum_{j<N} p[j]) / N        (Abel summation)
//   f4 = sum cum(dx)*dx    = 0.5 * (f1^2 + sum dx^2)            (closed form)
//   f6 = sum dx^2
//   f8 = sum dx^3
// Time-only features cancel exactly between real/gen -> skipped.
// loss = sum_i (mean_real f_i - mean_gen f_i)^2
//
// Single kernel. Cross-block reduction uses int64 fixed-point atomics:
// integer addition is associative -> deterministic regardless of block order.
// Only tid0 of each block touches the atomics (no block-wide fence wait).

#define T_LEN    4096
#define NROWS    4096
#define NBLOCKS  (2 * NROWS)
#define RT       128                  // threads per row block (4 warps)
#define WELEMS   1024                 // contiguous floats owned per warp
#define NFEAT    5
#define FP_SCALE 268435456.0          // 2^28 fixed-point scale

__device__ unsigned long long g_acc[NFEAT];   // signed fixed-point sums (2's complement)
__device__ int g_ctr = 0;                      // self-resets each launch

// ---- packed f32x2 helpers (Blackwell; only reachable via PTX) ----
__device__ __forceinline__ unsigned long long pk2(float lo, float hi) {
    unsigned long long r;
    asm("mov.b64 %0, {%1, %2};" : "=l"(r) : "f"(lo), "f"(hi));
    return r;
}
__device__ __forceinline__ void upk2(unsigned long long p, float& lo, float& hi) {
    asm("mov.b64 {%0, %1}, %2;" : "=f"(lo), "=f"(hi) : "l"(p));
}
__device__ __forceinline__ unsigned long long fma2(unsigned long long a,
                                                   unsigned long long b,
                                                   unsigned long long c) {
    unsigned long long d;
    asm("fma.rn.f32x2 %0, %1, %2, %3;" : "=l"(d) : "l"(a), "l"(b), "l"(c));
    return d;
}
__device__ __forceinline__ unsigned long long add2(unsigned long long a,
                                                   unsigned long long b) {
    unsigned long long d;
    asm("add.rn.f32x2 %0, %1, %2;" : "=l"(d) : "l"(a), "l"(b));
    return d;
}
__device__ __forceinline__ unsigned long long mul2(unsigned long long a,
                                                   unsigned long long b) {
    unsigned long long d;
    asm("mul.rn.f32x2 %0, %1, %2;" : "=l"(d) : "l"(a), "l"(b));
    return d;
}

__global__ __launch_bounds__(RT) void sigmmd_fused_kernel(
    const float* __restrict__ real_paths,
    const float* __restrict__ gen_paths,
    float* __restrict__ out)
{
    const int bid = blockIdx.x;
    const float* base = (bid < NROWS) ? real_paths : gen_paths;
    const int row = bid & (NROWS - 1);
    const float* p = base + (size_t)row * T_LEN;
    const int tid  = threadIdx.x;
    const int lane = tid & 31;
    const int w    = tid >> 5;

    __shared__ float s_w[RT / 32][3];

    // ---- Row feature computation (warp-coalesced float4 streaming) ----
    const float4* b4 = (const float4*)p + w * (WELEMS / 4);
    float4 v[8];
#pragma unroll
    for (int i = 0; i < 8; i++) v[i] = __ldcs(b4 + i * 32 + lane);

    // Predecessor of this warp's first element (only lane 0 uses it).
    // Warp 0 lane 0: phantom dx = 0 (prev = first element itself).
    float carry = 0.f;
    if (lane == 0) carry = (w == 0) ? v[0].x : __ldcs(p + w * WELEMS - 1);

    const unsigned long long NEG1 = pk2(-1.0f, -1.0f);
    unsigned long long qp = 0ull, cp = 0ull, spp = 0ull;
#pragma unroll
    for (int i = 0; i < 8; i++) {
        float4 c4 = v[i];
        float pl = __shfl_up_sync(0xffffffffu, c4.w, 1);
        float prev = (lane == 0) ? carry : pl;
        unsigned long long cur0 = pk2(c4.x, c4.y);
        unsigned long long cur1 = pk2(c4.z, c4.w);
        unsigned long long prv0 = pk2(prev, c4.x);
        unsigned long long prv1 = pk2(c4.y, c4.z);
        unsigned long long dx0 = fma2(prv0, NEG1, cur0);   // cur - prv
        unsigned long long dx1 = fma2(prv1, NEG1, cur1);
        unsigned long long t0 = mul2(dx0, dx0);
        unsigned long long t1 = mul2(dx1, dx1);
        qp  = add2(qp, add2(t0, t1));                      // sum dx^2
        cp  = fma2(t0, dx0, cp);                           // sum dx^3
        cp  = fma2(t1, dx1, cp);
        spp = add2(spp, add2(cur0, cur1));                 // sum p
        carry = __shfl_sync(0xffffffffu, c4.w, 31);
    }
    float ql, qh, cl, ch, sl, sh;
    upk2(qp, ql, qh); upk2(cp, cl, ch); upk2(spp, sl, sh);
    float q = ql + qh, c = cl + ch, sp = sl + sh;
    if (tid == RT - 1) sp -= v[7].w;   // sum p covers p[0..N-1] only

#pragma unroll
    for (int off = 16; off; off >>= 1) {
        q  += __shfl_down_sync(0xffffffffu, q,  off);
        c  += __shfl_down_sync(0xffffffffu, c,  off);
        sp += __shfl_down_sync(0xffffffffu, sp, off);
    }
    if (lane == 0) { s_w[w][0] = q; s_w[w][1] = c; s_w[w][2] = sp; }
    __syncthreads();
    // Warps 1..3 are done: they retire now. Only tid0 continues.
    if (tid != 0) return;

    double Q = 0, C = 0, SP = 0;
#pragma unroll
    for (int k = 0; k < RT / 32; k++) {
        Q  += (double)s_w[k][0];
        C  += (double)s_w[k][1];
        SP += (double)s_w[k][2];
    }
    double p0 = (double)v[0].x;
    double pN = (double)__ldg(p + T_LEN - 1);
    double S1 = pN - p0;
    const double sgn = (bid < NROWS) ? FP_SCALE : -FP_SCALE;

    // Deterministic integer accumulation (associative -> order-independent).
    long long fi[NFEAT];
    fi[0] = __double2ll_rn(sgn * S1);
    fi[1] = __double2ll_rn(sgn * (pN - SP / 4095.0));
    fi[2] = __double2ll_rn(sgn * (0.5 * (S1 * S1 + Q)));
    fi[3] = __double2ll_rn(sgn * Q);
    fi[4] = __double2ll_rn(sgn * C);
#pragma unroll
    for (int i = 0; i < NFEAT; i++)
        atomicAdd(&g_acc[i], (unsigned long long)fi[i]);

    __threadfence();   // order feature atomics before the counter bump
    if (atomicAdd(&g_ctr, 1) == NBLOCKS - 1) {
        // Last block standing: read totals (L2-coherent via atomic read).
        double loss = 0.0;
#pragma unroll
        for (int i = 0; i < NFEAT; i++) {
            long long t = (long long)atomicAdd(&g_acc[i], 0ull);
            double m = ((double)t / FP_SCALE) / (double)NROWS;
            loss += m * m;
        }
        out[0] = (float)loss;
        // Reset for the next graph replay.
#pragma unroll
        for (int i = 0; i < NFEAT; i++) g_acc[i] = 0ull;
        g_ctr = 0;
    }
}

extern "C" void kernel_launch(void* const* d_in, const int* in_sizes, int n_in,
                              void* d_out, int out_size)
{
    const float* real_paths = (const float*)d_in[0];
    const float* gen_paths  = (const float*)d_in[1];
    float* out = (float*)d_out;

    sigmmd_fused_kernel<<<NBLOCKS, RT>>>(real_paths, gen_paths, out);
}